// round 12
// baseline (speedup 1.0000x reference)
#include <cuda_runtime.h>
#include <math.h>

#define BSZ 16
#define SEQ 2048
#define HID 1024
#define NSP_PER_B 32
#define NCLS 8
#define NLBL 3
#define NSPAN (BSZ * NSP_PER_B)   // 512
#define H4 (HID / 4)              // 256
#define CHUNKS 2
#define NGRID (NSPAN * CHUNKS)    // 1024

// Stage A: per-(span,logit) word = (fixed-point biased partial sum << 3)|count
#define A_SCALE 1073741824.0      // 2^30
#define A_BIAS  128.0
// Stage L: per-span word, 3 x 20-bit logit fields + 3-bit counter
#define L_SCALE 65536.0           // 2^16
#define L_BIAS  8.0
// Stage G: global packed loss word (R8-proven)
#define G_VALID_SHIFT 10
#define G_FIX_SHIFT 20
#define G_ARRIVE_MASK 0x3FFULL
#define G_SCALE 1073741824.0      // 2^30

__device__ unsigned long long g_A[NSPAN * NLBL];  // reset by finishers
__device__ unsigned long long g_L[NSPAN];         // reset by finishers
__device__ unsigned long long g_G = 0ULL;         // reset by final finisher

// Each CTA pools a half-span (31-32 rows) over H, dots with W[c] -> 3 partials.
// All cross-CTA combining flows through relaxed 64-bit atomicAdd return values
// (bit-deterministic, no fences/acquires). Grid 1024 @ occ 6: 888 resident +
// 136 backfill CTAs -> per-SM byte balance, killing the 4.7us straggler tail.
__global__ __launch_bounds__(256, 6)
void fused_kernel(const float* __restrict__ enc,
                  const float* __restrict__ W,
                  const float* __restrict__ bias,
                  const int* __restrict__ head,
                  const int* __restrict__ tail,
                  const int* __restrict__ cls,
                  const int* __restrict__ labels,
                  float* __restrict__ out,       // [NSPAN*NLBL] logits, then loss
                  int write_loss)
{
    const int span = blockIdx.x >> 1;           // 0..511
    const int half = blockIdx.x & 1;            // 0..1
    const int b    = span / NSP_PER_B;
    const int s0   = head[span] + 1;
    const int n    = tail[span] - s0;           // full span length (63)
    const int c    = cls[span];
    const int tid  = threadIdx.x;               // 256 threads, 1 float4 col each

    const int lo = (n * half) >> 1;
    const int hi = (n * (half + 1)) >> 1;
    const int m  = hi - lo;                     // 31 or 32 rows

    const float4* base = reinterpret_cast<const float4*>(enc)
                       + ((long)b * SEQ + s0 + lo) * H4 + tid;

    // Tree-reduce single accumulator (regs ~40 -> occ 6); streaming loads.
    float4 acc = make_float4(0.f, 0.f, 0.f, 0.f);
    int s = 0;
    for (; s + 4 <= m; s += 4) {
        float4 v0 = __ldcs(base + (s + 0) * H4);
        float4 v1 = __ldcs(base + (s + 1) * H4);
        float4 v2 = __ldcs(base + (s + 2) * H4);
        float4 v3 = __ldcs(base + (s + 3) * H4);
        float x01 = v0.x + v1.x, x23 = v2.x + v3.x;
        float y01 = v0.y + v1.y, y23 = v2.y + v3.y;
        float z01 = v0.z + v1.z, z23 = v2.z + v3.z;
        float w01 = v0.w + v1.w, w23 = v2.w + v3.w;
        acc.x += x01 + x23;
        acc.y += y01 + y23;
        acc.z += z01 + z23;
        acc.w += w01 + w23;
    }
    for (; s < m; ++s) {
        float4 v = __ldcs(base + s * H4);
        acc.x += v.x; acc.y += v.y; acc.z += v.z; acc.w += v.w;
    }

    // W is (C, H, L): this thread's 4 H-cols are 12 contiguous floats.
    const float4* w4 = reinterpret_cast<const float4*>(W + (long)c * HID * NLBL)
                     + tid * 3;
    float4 w0 = w4[0], w1 = w4[1], w2 = w4[2];
    float p0 = acc.x * w0.x + acc.y * w0.w + acc.z * w1.z + acc.w * w2.y;
    float p1 = acc.x * w0.y + acc.y * w1.x + acc.z * w1.w + acc.w * w2.z;
    float p2 = acc.x * w0.z + acc.y * w1.y + acc.z * w2.x + acc.w * w2.w;

    #pragma unroll
    for (int off = 16; off > 0; off >>= 1) {
        p0 += __shfl_down_sync(0xffffffffu, p0, off);
        p1 += __shfl_down_sync(0xffffffffu, p1, off);
        p2 += __shfl_down_sync(0xffffffffu, p2, off);
    }
    __shared__ float sm[3][8];
    const int warp = tid >> 5, lane = tid & 31;
    if (lane == 0) { sm[0][warp] = p0; sm[1][warp] = p1; sm[2][warp] = p2; }
    __syncthreads();

    if (tid != 0) return;                       // serial tail: one thread/CTA

    float t[3] = {0.f, 0.f, 0.f};
    #pragma unroll
    for (int w = 0; w < 8; ++w) {
        t[0] += sm[0][w]; t[1] += sm[1][w]; t[2] += sm[2][w];
    }

    // ---- Stage A: publish partials; all 3 RMWs issued before any check ----
    unsigned long long ca[3], oa[3];
    #pragma unroll
    for (int k = 0; k < NLBL; ++k) {
        unsigned long long fix =
            (unsigned long long)(((double)t[k] + A_BIAS) * A_SCALE + 0.5);
        ca[k] = (fix << 3) | 1ULL;
    }
    oa[0] = atomicAdd(&g_A[span * NLBL + 0], ca[0]);
    oa[1] = atomicAdd(&g_A[span * NLBL + 1], ca[1]);
    oa[2] = atomicAdd(&g_A[span * NLBL + 2], ca[2]);

    const float inv = 1.0f / (float)n;
    #pragma unroll
    for (int k = 0; k < NLBL; ++k) {
        if ((oa[k] & 7ULL) != (unsigned long long)(CHUNKS - 1)) continue;
        // 2nd arriver on (span,k): owns the exact fixed-point total.
        unsigned long long tot = oa[k] + ca[k];
        double sumk = (double)(tot >> 3) / A_SCALE - (double)CHUNKS * A_BIAS;
        float lk = (float)sumk * inv + bias[c * NLBL + k];
        out[span * NLBL + k] = lk;
        g_A[span * NLBL + k] = 0ULL;            // reset for next replay
        if (!write_loss) continue;

        // ---- Stage L: gather this span's 3 logits ----
        unsigned long long lf =
            (unsigned long long)(((double)lk + L_BIAS) * L_SCALE + 0.5);
        unsigned long long cl = (lf << (3 + k * 20)) | 1ULL;
        unsigned long long ol = atomicAdd(&g_L[span], cl);
        if ((ol & 7ULL) != (unsigned long long)(NLBL - 1)) continue;
        // 3rd arriver: has all three (quantized) logits of this span.
        unsigned long long tl = ol + cl;
        float l0 = (float)((double)((tl >>  3) & 0xFFFFFULL) / L_SCALE - L_BIAS);
        float l1 = (float)((double)((tl >> 23) & 0xFFFFFULL) / L_SCALE - L_BIAS);
        float l2 = (float)((double)((tl >> 43) & 0xFFFFFULL) / L_SCALE - L_BIAS);
        g_L[span] = 0ULL;                       // reset for next replay

        int lab = labels[span];
        unsigned long long cg = 1ULL;           // arrival ticket
        if (lab >= 0) {
            float mx  = fmaxf(l0, fmaxf(l1, l2));
            float lse = mx + logf(expf(l0 - mx) + expf(l1 - mx) + expf(l2 - mx));
            float lv  = (lab == 0) ? l0 : ((lab == 1) ? l1 : l2);
            unsigned long long fix =
                (unsigned long long)((double)(lse - lv) * G_SCALE + 0.5);
            cg |= (fix << G_FIX_SHIFT) | (1ULL << G_VALID_SHIFT);
        }
        // ---- Stage G: global packed loss accumulator ----
        unsigned long long og = atomicAdd(&g_G, cg);
        if ((og & G_ARRIVE_MASK) == (unsigned long long)(NSPAN - 1)) {
            unsigned long long tg = og + cg;
            double lsum  = (double)(tg >> G_FIX_SHIFT) / G_SCALE;
            double valid = (double)((tg >> G_VALID_SHIFT) & G_ARRIVE_MASK);
            out[NSPAN * NLBL] = (float)(lsum / valid);
            g_G = 0ULL;                         // reset for next replay
        }
    }
}

extern "C" void kernel_launch(void* const* d_in, const int* in_sizes, int n_in,
                              void* d_out, int out_size)
{
    const float* enc  = (const float*)d_in[0];   // (16,2048,1024)
    const float* W    = (const float*)d_in[1];   // (8,1024,3)
    const float* bias = (const float*)d_in[2];   // (8,3)
    const int*   head = (const int*)d_in[3];     // (16,32)
    const int*   tail = (const int*)d_in[4];     // (16,32)
    const int*   cls  = (const int*)d_in[5];     // (16,32)
    const int*   lab  = (const int*)d_in[6];     // (16,32)
    float* out = (float*)d_out;

    int write_loss = (out_size > NSPAN * NLBL) ? 1 : 0;
    fused_kernel<<<NGRID, 256>>>(enc, W, bias, head, tail, cls, lab, out, write_loss);
}

// round 15
// speedup vs baseline: 1.0778x; 1.0778x over previous
#include <cuda_runtime.h>
#include <math.h>

#define BSZ 16
#define SEQ 2048
#define HID 1024
#define NSP_PER_B 32
#define NCLS 8
#define NLBL 3
#define NSPAN (BSZ * NSP_PER_B)   // 512
#define H4 (HID / 4)              // 256
#define CHUNKS 4
#define NGRID (NSPAN * CHUNKS)    // 2048

// Per-span packed partial words (2 per span). Contributors = chunks 0..2.
//   wordA = (fix(p0) << 34) | (fix(p1) << 4) | 1      (30-bit fields)
//   wordB = (fix(p2) << 4) | 1
// fix(x) = (x + A_BIAS) * A_SCALE; 3 contributions of <= 64*2^22 fit in 30 bits.
#define A_SCALE 4194304.0         // 2^22
#define A_BIAS  32.0              // partials ~N(0,2.6): 12-sigma margin
#define A_MASK  0x3FFFFFFFULL

// Stage G: global packed loss word (R8-proven)
#define G_VALID_SHIFT 10
#define G_FIX_SHIFT 20
#define G_ARRIVE_MASK 0x3FFULL
#define G_SCALE 1073741824.0      // 2^30

__device__ unsigned long long g_W[NSPAN * 2];   // reset by span combiners
__device__ unsigned long long g_G = 0ULL;       // reset by final finisher

// Each CTA pools ~16 rows of one span over H, dots with W[c] -> 3 partials.
// Chunks 0..2 publish via red.relaxed (NO return -> CTA retires immediately;
// the return-dependency retirement stall is what killed earlier chunked
// rounds). Chunk 3 spins on the packed words, combines, writes logits, and
// runs the single return-checked stage-G atomic for the loss.
__global__ __launch_bounds__(256, 6)
void fused_kernel(const float* __restrict__ enc,
                  const float* __restrict__ W,
                  const float* __restrict__ bias,
                  const int* __restrict__ head,
                  const int* __restrict__ tail,
                  const int* __restrict__ cls,
                  const int* __restrict__ labels,
                  float* __restrict__ out,       // [NSPAN*NLBL] logits, then loss
                  int write_loss)
{
    const int span  = blockIdx.x >> 2;          // 0..511
    const int chunk = blockIdx.x & 3;           // 0..3; 3 = combiner
    const int b     = span / NSP_PER_B;
    const int s0    = head[span] + 1;
    const int n     = tail[span] - s0;          // full span length (63)
    const int c     = cls[span];
    const int tid   = threadIdx.x;              // 256 threads, 1 float4 col each

    const int lo = (n * chunk) >> 2;
    const int hi = (n * (chunk + 1)) >> 2;
    const int m  = hi - lo;                     // rows in this chunk (~15-17)

    const float4* base = reinterpret_cast<const float4*>(enc)
                       + ((long)b * SEQ + s0 + lo) * H4 + tid;

    // R5-proven loop: 4 loads in flight, tree-reduce into one accumulator.
    float4 acc = make_float4(0.f, 0.f, 0.f, 0.f);
    int s = 0;
    for (; s + 4 <= m; s += 4) {
        float4 v0 = base[(s + 0) * H4];
        float4 v1 = base[(s + 1) * H4];
        float4 v2 = base[(s + 2) * H4];
        float4 v3 = base[(s + 3) * H4];
        float x01 = v0.x + v1.x, x23 = v2.x + v3.x;
        float y01 = v0.y + v1.y, y23 = v2.y + v3.y;
        float z01 = v0.z + v1.z, z23 = v2.z + v3.z;
        float w01 = v0.w + v1.w, w23 = v2.w + v3.w;
        acc.x += x01 + x23;
        acc.y += y01 + y23;
        acc.z += z01 + z23;
        acc.w += w01 + w23;
    }
    for (; s < m; ++s) {
        float4 v = base[s * H4];
        acc.x += v.x; acc.y += v.y; acc.z += v.z; acc.w += v.w;
    }

    // W is (C, H, L): this thread's 4 H-cols are 12 contiguous floats.
    const float4* w4 = reinterpret_cast<const float4*>(W + (long)c * HID * NLBL)
                     + tid * 3;
    float4 w0 = w4[0], w1 = w4[1], w2 = w4[2];
    float p0 = acc.x * w0.x + acc.y * w0.w + acc.z * w1.z + acc.w * w2.y;
    float p1 = acc.x * w0.y + acc.y * w1.x + acc.z * w1.w + acc.w * w2.z;
    float p2 = acc.x * w0.z + acc.y * w1.y + acc.z * w2.x + acc.w * w2.w;

    #pragma unroll
    for (int off = 16; off > 0; off >>= 1) {
        p0 += __shfl_down_sync(0xffffffffu, p0, off);
        p1 += __shfl_down_sync(0xffffffffu, p1, off);
        p2 += __shfl_down_sync(0xffffffffu, p2, off);
    }
    __shared__ float sm[3][8];
    const int warp = tid >> 5, lane = tid & 31;
    if (lane == 0) { sm[0][warp] = p0; sm[1][warp] = p1; sm[2][warp] = p2; }
    __syncthreads();

    if (tid != 0) return;                       // serial tail: one thread/CTA

    float t0 = 0.f, t1 = 0.f, t2 = 0.f;
    #pragma unroll
    for (int w = 0; w < 8; ++w) { t0 += sm[0][w]; t1 += sm[1][w]; t2 += sm[2][w]; }

    unsigned long long* wA = &g_W[span * 2 + 0];
    unsigned long long* wB = &g_W[span * 2 + 1];

    if (chunk != 3) {
        // Publisher: fire-and-forget reductions (no return value -> RED,
        // CTA retires immediately, no ATOMG round-trip on the exit path).
        unsigned long long fa0 =
            (unsigned long long)(((double)t0 + A_BIAS) * A_SCALE + 0.5);
        unsigned long long fa1 =
            (unsigned long long)(((double)t1 + A_BIAS) * A_SCALE + 0.5);
        unsigned long long fa2 =
            (unsigned long long)(((double)t2 + A_BIAS) * A_SCALE + 0.5);
        unsigned long long cA = (fa0 << 34) | (fa1 << 4) | 1ULL;
        unsigned long long cB = (fa2 << 4) | 1ULL;
        asm volatile("red.relaxed.gpu.global.add.u64 [%0], %1;"
                     :: "l"(wA), "l"(cA) : "memory");
        asm volatile("red.relaxed.gpu.global.add.u64 [%0], %1;"
                     :: "l"(wB), "l"(cB) : "memory");
        return;
    }

    // ---- Combiner (chunk 3): spin until all 3 partners have published ----
    unsigned long long vA, vB;
    for (;;) {
        asm volatile("ld.relaxed.gpu.global.u64 %0, [%1];"
                     : "=l"(vA) : "l"(wA) : "memory");
        if ((vA & 0xFULL) == 3ULL) break;
        __nanosleep(64);
    }
    for (;;) {
        asm volatile("ld.relaxed.gpu.global.u64 %0, [%1];"
                     : "=l"(vB) : "l"(wB) : "memory");
        if ((vB & 0xFULL) == 3ULL) break;
        __nanosleep(64);
    }
    *wA = 0ULL;                                  // reset for next replay
    *wB = 0ULL;

    double s0d = (double)(vA >> 34)            / A_SCALE - 3.0 * A_BIAS;
    double s1d = (double)((vA >> 4) & A_MASK)  / A_SCALE - 3.0 * A_BIAS;
    double s2d = (double)((vB >> 4) & A_MASK)  / A_SCALE - 3.0 * A_BIAS;

    const float inv = 1.0f / (float)n;
    float l0 = (float)(s0d + (double)t0) * inv + bias[c * NLBL + 0];
    float l1 = (float)(s1d + (double)t1) * inv + bias[c * NLBL + 1];
    float l2 = (float)(s2d + (double)t2) * inv + bias[c * NLBL + 2];
    out[span * NLBL + 0] = l0;
    out[span * NLBL + 1] = l1;
    out[span * NLBL + 2] = l2;

    if (!write_loss) return;

    // ---- Stage G: R8-proven packed global loss accumulator ----
    int lab = labels[span];
    unsigned long long cg = 1ULL;
    if (lab >= 0) {
        float mx  = fmaxf(l0, fmaxf(l1, l2));
        float lse = mx + logf(expf(l0 - mx) + expf(l1 - mx) + expf(l2 - mx));
        float lv  = (lab == 0) ? l0 : ((lab == 1) ? l1 : l2);
        unsigned long long fix =
            (unsigned long long)((double)(lse - lv) * G_SCALE + 0.5);
        cg |= (fix << G_FIX_SHIFT) | (1ULL << G_VALID_SHIFT);
    }
    unsigned long long og = atomicAdd(&g_G, cg);
    if ((og & G_ARRIVE_MASK) == (unsigned long long)(NSPAN - 1)) {
        unsigned long long tg = og + cg;
        double lsum  = (double)(tg >> G_FIX_SHIFT) / G_SCALE;
        double valid = (double)((tg >> G_VALID_SHIFT) & G_ARRIVE_MASK);
        out[NSPAN * NLBL] = (float)(lsum / valid);
        g_G = 0ULL;                              // reset for next replay
    }
}

extern "C" void kernel_launch(void* const* d_in, const int* in_sizes, int n_in,
                              void* d_out, int out_size)
{
    const float* enc  = (const float*)d_in[0];   // (16,2048,1024)
    const float* W    = (const float*)d_in[1];   // (8,1024,3)
    const float* bias = (const float*)d_in[2];   // (8,3)
    const int*   head = (const int*)d_in[3];     // (16,32)
    const int*   tail = (const int*)d_in[4];     // (16,32)
    const int*   cls  = (const int*)d_in[5];     // (16,32)
    const int*   lab  = (const int*)d_in[6];     // (16,32)
    float* out = (float*)d_out;

    int write_loss = (out_size > NSPAN * NLBL) ? 1 : 0;
    fused_kernel<<<NGRID, 256>>>(enc, W, bias, head, tail, cls, lab, out, write_loss);
}